// round 17
// baseline (speedup 1.0000x reference)
#include <cuda_runtime.h>
#include <cuda_bf16.h>
#include <cstdint>

typedef unsigned long long ull;

#define CDIM 256
#define VDIM 25
#define NSAMP 2
#define PE_LEN 89
#define NEG_SLOPE 0.01f
#define NTHR 256

// ---- SMEM offsets from 1024-aligned base ----
#define H_OFF    0u
#define AS2_OFF  65536u      // 25 x 13 packed f32x2 A rows = 2600 B
#define BIAS_OFF 68608u      // 3 x 256 f32 = 3072 B
#define SMEM_DYN 72704u      // x2 CTAs = 145408 <= 227KB/SM

// ---------------------------------------------------------------------------
// helpers
// ---------------------------------------------------------------------------
__device__ __forceinline__ uint32_t smem_u32(const void* p) {
    uint32_t a;
    asm("{ .reg .u64 t; cvta.to.shared.u64 t, %1; cvt.u32.u64 %0, t; }"
        : "=r"(a) : "l"(p));
    return a;
}
__device__ __forceinline__ ull fma2(ull a, ull b, ull c) {
    ull d;
    asm("fma.rn.f32x2 %0, %1, %2, %3;" : "=l"(d) : "l"(a), "l"(b), "l"(c));
    return d;
}
__device__ __forceinline__ void ldsm4(uint32_t* r, uint32_t a) {
    asm volatile("ldmatrix.sync.aligned.m8n8.x4.shared.b16 {%0,%1,%2,%3}, [%4];"
        : "=r"(r[0]), "=r"(r[1]), "=r"(r[2]), "=r"(r[3]) : "r"(a));
}
__device__ __forceinline__ void mma_bf16(float* d, const uint32_t* a,
                                         const uint32_t* b) {
    asm volatile(
        "mma.sync.aligned.m16n8k16.row.col.f32.bf16.bf16.f32 "
        "{%0,%1,%2,%3}, {%4,%5,%6,%7}, {%8,%9}, {%0,%1,%2,%3};"
        : "+f"(d[0]), "+f"(d[1]), "+f"(d[2]), "+f"(d[3])
        : "r"(a[0]), "r"(a[1]), "r"(a[2]), "r"(a[3]), "r"(b[0]), "r"(b[1]));
}
__device__ __forceinline__ void sts_f32(uint32_t a, float v) {
    asm volatile("st.shared.f32 [%0], %1;" :: "r"(a), "f"(v));
}
__device__ __forceinline__ float lds_f32(uint32_t a) {
    float v; asm volatile("ld.shared.f32 %0, [%1];" : "=f"(v) : "r"(a)); return v;
}
__device__ __forceinline__ void sts_u16(uint32_t a, uint16_t v) {
    asm volatile("st.shared.u16 [%0], %1;" :: "r"(a), "h"(v));
}
__device__ __forceinline__ ull lds_u64(uint32_t a) {
    ull v; asm volatile("ld.shared.b64 %0, [%1];" : "=l"(v) : "r"(a)); return v;
}
__device__ __forceinline__ void sts_u64(uint32_t a, ull v) {
    asm volatile("st.shared.b64 [%0], %1;" :: "r"(a), "l"(v));
}

// H tile: [n row] x [k (0..511)] bf16, 1024 B rows, XOR-swizzled
__device__ __forceinline__ uint32_t h_addr(uint32_t hb, int n, int k) {
    return hb + n * 1024 + ((((k >> 3) ^ (n & 7)) << 4) | ((k & 7) << 1));
}
// D (fp32) overlay in H region: [n][o], XOR-swizzled
__device__ __forceinline__ uint32_t d_addr(uint32_t hb, int n, int o) {
    return hb + n * 1024 + ((o ^ ((n & 7) << 2)) << 2);
}

__device__ __forceinline__ void split2(float v, uint16_t& hi, uint16_t& lo) {
    __nv_bfloat16 h = __float2bfloat16(v);
    __nv_bfloat16 l = __float2bfloat16(v - __bfloat162float(h));
    hi = __bfloat16_as_ushort(h);
    lo = __bfloat16_as_ushort(l);
}

// ---------------------------------------------------------------------------
// device globals + merged prep kernel
// g_wf: W in MMA-fragment-major layout: [lp = layer*2+part][mtile][ktile][lane]
// ---------------------------------------------------------------------------
__device__ float g_pe[PE_LEN * CDIM];
__device__ uint4 g_wf[6 * 16 * 16 * 32];            // 768 KB, L2-resident

#define PE_N   (PE_LEN * CDIM)                      // 22784
#define WF_N   (6 * 16 * 16 * 32)                   // 49152

__global__ void prep_kernel(const float* __restrict__ w1,
                            const float* __restrict__ w2,
                            const float* __restrict__ wp) {
    int idx = blockIdx.x * blockDim.x + threadIdx.x;
    if (idx < PE_N) {
        int row = idx / CDIM, c = idx % CDIM;
        int p2 = (c >> 1) * 2;
        float divf = expf((float)p2 * (-9.210340371976184f / 256.0f));
        double ang = (double)row * (double)divf;
        g_pe[idx] = (c & 1) ? (float)cos(ang) : (float)sin(ang);
    } else if (idx < PE_N + WF_N) {
        int t = idx - PE_N;
        int lane = t & 31, kt = (t >> 5) & 15, mt = (t >> 9) & 15, lp = t >> 13;
        int l = lp >> 1, part = lp & 1;
        const float* w = (l == 0) ? w1 : ((l == 1) ? w2 : wp);
        int r = lane >> 2, c0 = (lane & 3) * 2;
        uint32_t q[4];
#pragma unroll
        for (int m = 0; m < 4; m++) {
            int row = mt * 16 + r + ((m & 1) << 3);
            int col = kt * 16 + c0 + ((m >> 1) << 3);
            uint16_t h0, l0, h1, l1;
            split2(w[row * 256 + col], h0, l0);
            split2(w[row * 256 + col + 1], h1, l1);
            uint16_t e0 = part ? l0 : h0, e1 = part ? l1 : h1;
            q[m] = (uint32_t)e0 | ((uint32_t)e1 << 16);
        }
        g_wf[t] = make_uint4(q[0], q[1], q[2], q[3]);
    }
}

// fragment fetch: 4 m-tiles (m=64 per warp); one LDG.128 per tile
__device__ __forceinline__ void load_a(uint4* dst, int s, int mt0, int lane) {
    const uint4* wf = g_wf + (size_t)(s >> 4) * 8192 + (size_t)(s & 15) * 32
                    + lane;
#pragma unroll
    for (int i = 0; i < 4; i++)
        dst[i] = __ldg(wf + (size_t)(mt0 + i) * 512);
}

// ---------------------------------------------------------------------------
// main kernel: 1 CTA = 2 samples (rows n = s*25+v); 256 threads = 8 warps,
// warp grid 4(m=64) x 2(n: j-tiles 0-3 / 4-6) -> H ldsm halved vs 8x1.
// Barrier-free GEMM loop (W via LDG from L2-hot frag table); 2 CTAs/SM.
// ---------------------------------------------------------------------------
__global__ void __launch_bounds__(NTHR, 2)
ode_main(const float* __restrict__ x, const float* __restrict__ A,
         const float* __restrict__ b1, const float* __restrict__ b2,
         const float* __restrict__ bp, const int* __restrict__ tptr,
         float* __restrict__ out) {
    extern __shared__ char raw[];
    uint32_t rawu = smem_u32(raw);
    uint32_t base = (rawu + 1023u) & ~1023u;

    const int tid = threadIdx.x, lane = tid & 31, wid = tid >> 5;
    const int blk = blockIdx.x;
    const uint32_t hb = base + H_OFF;
    const int ob = (wid & 3) * 64;      // warp m origin (o), 4 m-warps
    const int n_sel = wid >> 2;         // 0: j-tiles 0..3, 1: j-tiles 4..6
    const int jn = n_sel ? 3 : 4;       // j-tiles this warp computes
    const int mt0 = (wid & 3) * 4;      // first m16-tile index

    // stage A (packed f32x2 rows) + biases
    for (int i = tid; i < VDIM * 13; i += NTHR) {
        int v = i / 13, j = i % 13, u0 = 2 * j, u1 = 2 * j + 1;
        float f0 = A[v * VDIM + u0];
        float f1 = (u1 < VDIM) ? A[v * VDIM + u1] : 0.f;
        ull p = (ull)__float_as_uint(f0) | ((ull)__float_as_uint(f1) << 32);
        sts_u64(base + AS2_OFF + i * 8, p);
    }
    for (int i = tid; i < 768; i += NTHR) {
        float bv = (i < 256) ? b1[i] : ((i < 512) ? b2[i - 256] : bp[i - 512]);
        sts_f32(base + BIAS_OFF + i * 4, bv);
    }

    // build H = split(x + pe): rows n = s*25+v
    const int t0 = *tptr;
    for (int i = tid; i < NSAMP * CDIM * VDIM; i += NTHR) {
        int s = i / (CDIM * VDIM);
        int rem = i - s * (CDIM * VDIM);
        int c = rem / VDIM, v = rem - c * VDIM;
        int n = blk * NSAMP + s;
        float val = x[(size_t)n * (CDIM * VDIM) + rem]
                  + g_pe[(t0 + (n & 63)) * CDIM + c];
        uint16_t hi, lo;
        split2(val, hi, lo);
        int nr = s * VDIM + v;
        sts_u16(h_addr(hb, nr, c), hi);
        sts_u16(h_addr(hb, nr, 256 + c), lo);
    }
    __syncthreads();

    float acc[4][4][4];
#pragma unroll
    for (int i = 0; i < 4; i++)
#pragma unroll
        for (int j = 0; j < 4; j++)
#pragma unroll
            for (int e = 0; e < 4; e++) acc[i][j][e] = 0.f;

    // 96 steps: 3 layers x {part0(Wh): kt 0..15, part1(Wl): kt 0..15}
    uint4 a0[4], a1[4];
    load_a(a0, 0, mt0, lane);
    load_a(a1, 1, mt0, lane);

#pragma unroll 2
    for (int s = 0; s < 96; s++) {
        const int part = (s >> 4) & 1;
        const int kt = s & 15;

#pragma unroll
        for (int tgt = 0; tgt < 2; tgt++) {
            if (part && tgt) break;                  // Wl: Hh only
            int kh = (part ? 0 : tgt * 256) + kt * 16;
            uint32_t b[4][2];
            {
                int sel = lane >> 3;
                int n0 = (lane & 7) + ((sel >> 1) << 3) + (n_sel << 5);
                int k = kh + ((sel & 1) << 3);
#pragma unroll
                for (int jj = 0; jj < 2; jj++) {
                    uint32_t r[4];
                    ldsm4(r, h_addr(hb, n0 + jj * 16, k));
                    b[2 * jj][0] = r[0]; b[2 * jj][1] = r[1];
                    b[2 * jj + 1][0] = r[2]; b[2 * jj + 1][1] = r[3];
                }
            }
#pragma unroll
            for (int i = 0; i < 4; i++)
#pragma unroll
                for (int j = 0; j < 4; j++)
                    if (j < 3 || !n_sel)             // n=1 warps: 3 j-tiles
                        mma_bf16(acc[i][j], (const uint32_t*)&a0[i], b[j]);
        }

        // rotate prefetch pipeline (2-deep)
#pragma unroll
        for (int i = 0; i < 4; i++) a0[i] = a1[i];
        int sn = (s + 2 < 96) ? s + 2 : 95;
        load_a(a1, sn, mt0, lane);

        if ((s & 31) == 31) {            // ---- layer epilogue ----
            const int l = s >> 5;
            if (l < 2) {
                __syncthreads();         // all warps done reading H this layer
                // 1) acc -> D (fp32 overlay on H region), real rows only
#pragma unroll
                for (int i = 0; i < 4; i++) {
                    int o = ob + i * 16 + (lane >> 2);
#pragma unroll
                    for (int j = 0; j < 4; j++) {
                        if (j >= 3 && n_sel) continue;
                        int jg = (n_sel << 2) + j;
                        int n = jg * 8 + 2 * (lane & 3);
                        if (n < 50) {
                            sts_f32(d_addr(hb, n, o),     acc[i][j][0]);
                            sts_f32(d_addr(hb, n, o + 8), acc[i][j][2]);
                        }
                        if (n + 1 < 50) {
                            sts_f32(d_addr(hb, n + 1, o),     acc[i][j][1]);
                            sts_f32(d_addr(hb, n + 1, o + 8), acc[i][j][3]);
                        }
                    }
                }
                __syncthreads();
                // 2) channel o = tid; both samples' D rows into regs
                const int o = tid;
                ull du[NSAMP][13];
#pragma unroll
                for (int sm = 0; sm < NSAMP; sm++) {
                    float tv[26];
                    tv[25] = 0.f;
#pragma unroll
                    for (int u = 0; u < 25; u++)
                        tv[u] = lds_f32(d_addr(hb, sm * VDIM + u, o));
#pragma unroll
                    for (int j = 0; j < 13; j++)
                        du[sm][j] = (ull)__float_as_uint(tv[2 * j])
                                  | ((ull)__float_as_uint(tv[2 * j + 1]) << 32);
                }
                __syncthreads();
                // 3) A^T mult + bias + lrelu + re-split into H (v-outer)
                float bb = lds_f32(base + BIAS_OFF + (l * 256 + o) * 4);
#pragma unroll 5
                for (int v = 0; v < VDIM; v++) {
                    ull ar[13];
#pragma unroll
                    for (int j = 0; j < 13; j++)
                        ar[j] = lds_u64(base + AS2_OFF + (v * 13 + j) * 8);
#pragma unroll
                    for (int sm = 0; sm < NSAMP; sm++) {
                        ull accv = 0ull;
#pragma unroll
                        for (int j = 0; j < 13; j++)
                            accv = fma2(du[sm][j], ar[j], accv);
                        float a_0, a_1;
                        asm("mov.b64 {%0,%1}, %2;"
                            : "=f"(a_0), "=f"(a_1) : "l"(accv));
                        float rr = a_0 + a_1 + bb;
                        rr = (rr >= 0.f) ? rr : NEG_SLOPE * rr;
                        uint16_t hi, lo;
                        split2(rr, hi, lo);
                        int nr = sm * VDIM + v;
                        sts_u16(h_addr(hb, nr, o), hi);
                        sts_u16(h_addr(hb, nr, 256 + o), lo);
                    }
                }
                __syncthreads();
            } else {
                // final layer: bias + direct gmem store from fragments
#pragma unroll
                for (int i = 0; i < 4; i++) {
                    int o0 = ob + i * 16 + (lane >> 2);
                    float bb0 = lds_f32(base + BIAS_OFF + (512 + o0) * 4);
                    float bb1 = lds_f32(base + BIAS_OFF + (512 + o0 + 8) * 4);
#pragma unroll
                    for (int j = 0; j < 4; j++) {
                        if (j >= 3 && n_sel) continue;
                        int jg = (n_sel << 2) + j;
                        int n = jg * 8 + 2 * (lane & 3);
#pragma unroll
                        for (int e = 0; e < 2; e++) {
                            int r = n + e;
                            if (r < NSAMP * VDIM) {
                                int sm = (r >= VDIM) ? 1 : 0;
                                int v = r - sm * VDIM;
                                size_t o_base =
                                    ((size_t)(blk * NSAMP + sm)) * (CDIM * VDIM);
                                out[o_base + o0 * VDIM + v]
                                    = acc[i][j][e] + bb0;
                                out[o_base + (o0 + 8) * VDIM + v]
                                    = acc[i][j][e + 2] + bb1;
                            }
                        }
                    }
                }
            }
            // reset accumulators for next layer
#pragma unroll
            for (int i = 0; i < 4; i++)
#pragma unroll
                for (int j = 0; j < 4; j++)
#pragma unroll
                    for (int e = 0; e < 4; e++) acc[i][j][e] = 0.f;
        }
    }
}

// ---------------------------------------------------------------------------
extern "C" void kernel_launch(void* const* d_in, const int* in_sizes, int n_in,
                              void* d_out, int out_size) {
    const float* x  = (const float*)d_in[0];
    const float* A  = (const float*)d_in[1];
    const float* w1 = (const float*)d_in[2];
    const float* b1 = (const float*)d_in[3];
    const float* w2 = (const float*)d_in[4];
    const float* b2 = (const float*)d_in[5];
    const float* wp = (const float*)d_in[6];
    const float* bp = (const float*)d_in[7];
    const int*   t  = (const int*)d_in[8];
    float* out = (float*)d_out;

    const int B = in_sizes[0] / (CDIM * VDIM);   // 4096

    cudaFuncSetAttribute(ode_main, cudaFuncAttributeMaxDynamicSharedMemorySize,
                         SMEM_DYN);

    prep_kernel<<<(PE_N + WF_N + 255) / 256, 256>>>(w1, w2, wp);
    ode_main<<<B / NSAMP, NTHR, SMEM_DYN>>>(x, A, b1, b2, bp, t, out);
}